// round 3
// baseline (speedup 1.0000x reference)
#include <cuda_runtime.h>
#include <math.h>

#define EMAX 4096
#define CAP (EMAX*(EMAX-1)/2)   // 8386560 worst-case pairs

// ---- device scratch (no allocations allowed) ----
__device__ float g_ang[EMAX];
__device__ float g_nx[EMAX], g_ny[EMAX], g_c[EMAX], g_mx[EMAX], g_my[EMAX];
__device__ float g_sang[EMAX];               // angle-sorted angles
__device__ unsigned short g_sidx[EMAX];      // original edge index per sorted slot
__device__ unsigned int g_count;
__device__ float g_buf[CAP];                 // compacted masked distances
__device__ unsigned int g_hist16[65536];     // pass-1 histogram (top 16 bits, shared by 3 ranks)
__device__ unsigned int g_hist16b[3*65536];  // pass-2 histograms (low 16 bits, per rank)
__device__ unsigned int g_pfx16[3];          // chosen top-16 bucket per rank
__device__ unsigned int g_rank[3];           // remaining rank within bucket
__device__ float g_qval[3];                  // final q1 / mu / q3
__device__ unsigned int g_done;
__device__ double g_sum;

#define PI_F  3.14159274101257324f
#define THR_F 0.08726646259971647f           /* radians(5.0) in f32 */

// ---------------------------------------------------------------------------
// Kernel 1: per-edge geometry + zero all scratch (wide grid).
// ---------------------------------------------------------------------------
__global__ void k_setup(const float* __restrict__ pos, const int* __restrict__ eidx, int E)
{
    int t = blockIdx.x * blockDim.x + threadIdx.x;
    int nthreads = gridDim.x * blockDim.x;

    if (t == 0) { g_count = 0u; g_sum = 0.0; g_done = 0u; }

    // zero histograms (grid-stride)
    for (int k = t; k < 65536; k += nthreads)       g_hist16[k]  = 0u;
    for (int k = t; k < 3*65536; k += nthreads)     g_hist16b[k] = 0u;

    int e = t;
    if (e >= E) return;

    int s = eidx[e];
    int d = eidx[E + e];
    float sx = pos[2*s], sy = pos[2*s+1];
    float dx = pos[2*d], dy = pos[2*d+1];
    float vx = dx - sx, vy = dy - sy;
    float len = sqrtf(vx*vx + vy*vy);
    len = fmaxf(len, 1e-8f);
    float ux = vx / len, uy = vy / len;

    // angle in [0, pi): python-style floor-mod of atan2
    float a = atan2f(uy, ux);
    a = fmodf(a, PI_F);
    if (a < 0.f) a += PI_F;
    g_ang[e] = a;

    float nx = -uy, ny = ux;
    g_nx[e] = nx;  g_ny[e] = ny;
    g_c[e]  = sx*nx + sy*ny;
    g_mx[e] = (sx + dx) * 0.5f;
    g_my[e] = (sy + dy) * 0.5f;
}

// ---------------------------------------------------------------------------
// Kernel 2: bitonic sort of (angle, idx), single block, shared memory.
// ---------------------------------------------------------------------------
__global__ void k_sort(int E)
{
    __shared__ float sa[EMAX];
    __shared__ unsigned short si[EMAX];

    for (int t = threadIdx.x; t < EMAX; t += blockDim.x) {
        sa[t] = (t < E) ? g_ang[t] : 3.4e38f;
        si[t] = (unsigned short)t;
    }
    __syncthreads();

    for (int k = 2; k <= EMAX; k <<= 1) {
        for (int j = k >> 1; j > 0; j >>= 1) {
            for (int t = threadIdx.x; t < EMAX; t += blockDim.x) {
                int p = t ^ j;
                if (p > t) {
                    bool up = ((t & k) == 0);
                    float va = sa[t], vb = sa[p];
                    if ((va > vb) == up) {
                        sa[t] = vb; sa[p] = va;
                        unsigned short ia = si[t]; si[t] = si[p]; si[p] = ia;
                    }
                }
            }
            __syncthreads();
        }
    }
    for (int t = threadIdx.x; t < EMAX; t += blockDim.x) {
        g_sang[t] = sa[t];
        g_sidx[t] = si[t];
    }
}

// ---------------------------------------------------------------------------
// Kernel 3: sorted pair sweep + fused pass-1 (top-16-bit) histogram.
// One warp per sorted edge i. Qualifying j (sorted, j>i) form a contiguous
// prefix (da<=THR) and contiguous wrap suffix (da>THR && PI-da<=THR).
// dist uses the ORIGINAL lower-index edge's line (matches reference).
// ---------------------------------------------------------------------------
__device__ __forceinline__ void emit_warp(unsigned full, bool in, float dist, int lane)
{
    unsigned ball = __ballot_sync(full, in);
    if (ball) {
        int leader = __ffs(ball) - 1;
        unsigned base = 0;
        if (lane == leader) base = atomicAdd(&g_count, (unsigned)__popc(ball));
        base = __shfl_sync(full, base, leader);
        if (in) {
            unsigned bits = __float_as_uint(dist);
            g_buf[base + __popc(ball & ((1u << lane) - 1u))] = dist;
            atomicAdd(&g_hist16[bits >> 16], 1u);        // pass-1 histogram, fused
        }
    }
}

__global__ void k_pairs2(int E)
{
    const unsigned FULL = 0xFFFFFFFFu;
    int wpb  = blockDim.x >> 5;
    int i    = blockIdx.x * wpb + (threadIdx.x >> 5);
    int lane = threadIdx.x & 31;
    if (i >= E - 1) return;

    float ai = g_sang[i];
    int   oi = g_sidx[i];

    // forward prefix: da <= THR
    for (int jb = i + 1; jb < E; jb += 32) {
        int  j     = jb + lane;
        bool in    = false;
        float dist = 0.f;
        if (j < E) {
            float aj = g_sang[j];
            float da = fabsf(ai - aj);
            if (da <= THR_F) {
                in = true;
                int oj = (int)g_sidx[j];
                int a = min(oi, oj), b = max(oi, oj);
                dist = fabsf(fmaf(g_nx[a], g_mx[b], fmaf(g_ny[a], g_my[b], -g_c[a])));
            }
        }
        emit_warp(FULL, in, dist, lane);
        if (__any_sync(FULL, !in)) break;   // monotone: first failure ends prefix
    }

    // backward suffix: da > THR && PI - da <= THR
    for (int jb = E - 1; jb > i; jb -= 32) {
        int  j     = jb - lane;
        bool in    = false;
        bool stop  = true;
        float dist = 0.f;
        if (j > i) {
            float aj = g_sang[j];
            float da = fabsf(ai - aj);
            stop = ((PI_F - da) > THR_F);
            if (!stop && da > THR_F) {
                in = true;
                int oj = (int)g_sidx[j];
                int a = min(oi, oj), b = max(oi, oj);
                dist = fabsf(fmaf(g_nx[a], g_mx[b], fmaf(g_ny[a], g_my[b], -g_c[a])));
            }
        }
        emit_warp(FULL, in, dist, lane);
        if (__any_sync(FULL, stop)) break;  // monotone: first failure ends suffix
    }
}

// ---------------------------------------------------------------------------
// Kernel 4: pass-1 selection. Compute ranks from n, scan 65536 bins (one
// block, 64 bins/thread + block scan), pick top-16 bucket for each rank.
// ---------------------------------------------------------------------------
__global__ void k_sel1()
{
    __shared__ unsigned scan[1024];
    int t = threadIdx.x;

    unsigned local = 0;
    const uint4* h4 = (const uint4*)g_hist16;
    #pragma unroll 4
    for (int k = 0; k < 16; k++) {
        uint4 v = h4[t*16 + k];
        local += v.x + v.y + v.z + v.w;
    }
    scan[t] = local;
    __syncthreads();
    #pragma unroll
    for (int off = 1; off < 1024; off <<= 1) {
        unsigned v = scan[t];
        unsigned a = (t >= off) ? scan[t - off] : 0u;
        __syncthreads();
        scan[t] = v + a;
        __syncthreads();
    }
    unsigned inc = scan[t], exc = inc - local;

    int n  = (int)g_count;
    int r0 = n/4 - 1;      if (r0 < 0)     r0 = 0;
    int r1 = n/2;
    int r2 = (3*n)/4;      if (r2 > n - 1) r2 = n - 1;
    if (r2 < 0) r2 = 0;
    unsigned rr[3] = {(unsigned)r0, (unsigned)r1, (unsigned)r2};

    #pragma unroll
    for (int s = 0; s < 3; s++) {
        unsigned r = rr[s];
        if (exc <= r && r < inc) {
            unsigned cum = exc;
            for (int b = t*64;; b++) {
                unsigned h = g_hist16[b];
                if (cum + h > r) { g_pfx16[s] = (unsigned)b; g_rank[s] = r - cum; break; }
                cum += h;
            }
        }
    }
}

// ---------------------------------------------------------------------------
// Kernel 5: pass-2 histogram — single scan of g_buf, low-16-bit bins for the
// elements matching each rank's top-16 prefix (few per prefix -> cheap).
// ---------------------------------------------------------------------------
__global__ void k_hist2()
{
    unsigned n  = g_count;
    unsigned p0 = g_pfx16[0], p1 = g_pfx16[1], p2 = g_pfx16[2];

    for (unsigned idx = blockIdx.x * blockDim.x + threadIdx.x; idx < n;
         idx += gridDim.x * blockDim.x) {
        unsigned bits = __float_as_uint(g_buf[idx]);
        unsigned hi = bits >> 16, lo = bits & 0xFFFFu;
        if (hi == p0) atomicAdd(&g_hist16b[lo],          1u);
        if (hi == p1) atomicAdd(&g_hist16b[65536  + lo], 1u);
        if (hi == p2) atomicAdd(&g_hist16b[131072 + lo], 1u);
    }
}

// ---------------------------------------------------------------------------
// Kernel 6: pass-2 selection. One block per statistic (gridDim.x = 3).
// ---------------------------------------------------------------------------
__global__ void k_sel2()
{
    __shared__ unsigned scan[1024];
    int s = blockIdx.x, t = threadIdx.x;
    const unsigned* H = &g_hist16b[s * 65536];

    unsigned local = 0;
    const uint4* h4 = (const uint4*)H;
    #pragma unroll 4
    for (int k = 0; k < 16; k++) {
        uint4 v = h4[t*16 + k];
        local += v.x + v.y + v.z + v.w;
    }
    scan[t] = local;
    __syncthreads();
    #pragma unroll
    for (int off = 1; off < 1024; off <<= 1) {
        unsigned v = scan[t];
        unsigned a = (t >= off) ? scan[t - off] : 0u;
        __syncthreads();
        scan[t] = v + a;
        __syncthreads();
    }
    unsigned inc = scan[t], exc = inc - local;

    unsigned r = g_rank[s];
    if (exc <= r && r < inc) {
        unsigned cum = exc;
        for (int b = t*64;; b++) {
            unsigned h = H[b];
            if (cum + h > r) {
                g_qval[s] = __uint_as_float((g_pfx16[s] << 16) | (unsigned)b);
                break;
            }
            cum += h;
        }
    }
}

// ---------------------------------------------------------------------------
// Kernel 7: hinge-loss sum (double accumulate) + fused finalize (last block).
// ---------------------------------------------------------------------------
__global__ void k_loss(float* __restrict__ out)
{
    unsigned n = g_count;
    float q1 = g_qval[0];
    float mu = g_qval[1];
    float q3 = g_qval[2];
    float margin = fmaxf(q3 - q1, 1e-6f) * 0.75f;   // iqr * 0.5 * 1.5

    double local = 0.0;
    for (unsigned idx = blockIdx.x * blockDim.x + threadIdx.x; idx < n;
         idx += gridDim.x * blockDim.x) {
        float d = g_buf[idx];
        float v = fabsf(d - mu) - margin;
        if (v > 0.f) local += (double)v;
    }

    for (int o = 16; o; o >>= 1) local += __shfl_down_sync(0xFFFFFFFFu, local, o);
    __shared__ double shs[32];
    if ((threadIdx.x & 31) == 0) shs[threadIdx.x >> 5] = local;
    __syncthreads();
    if (threadIdx.x < 32) {
        double v = (threadIdx.x < (blockDim.x + 31) / 32) ? shs[threadIdx.x] : 0.0;
        for (int o = 16; o; o >>= 1) v += __shfl_down_sync(0xFFFFFFFFu, v, o);
        if (threadIdx.x == 0 && v != 0.0) atomicAdd(&g_sum, v);
    }

    // last block finalizes the scalar output
    __shared__ bool last;
    if (threadIdx.x == 0) {
        __threadfence();
        unsigned d = atomicAdd(&g_done, 1u);
        last = (d == gridDim.x - 1);
    }
    __syncthreads();
    if (last && threadIdx.x == 0) {
        __threadfence();
        double denom = (double)(n > 0u ? n : 1u);
        out[0] = (float)(g_sum / denom);
    }
}

// ---------------------------------------------------------------------------
extern "C" void kernel_launch(void* const* d_in, const int* in_sizes, int n_in,
                              void* d_out, int out_size)
{
    const float* pos  = (const float*)d_in[0];   // node_positions (B*N, 2)
    // d_in[1] = adjacency: unused by the math
    const int*   eidx = (const int*)d_in[2];     // edge_index (2, E)
    float* out = (float*)d_out;

    int E = in_sizes[2] / 2;
    if (E > EMAX) E = EMAX;

    k_setup<<<128, 256>>>(pos, eidx, E);         // geometry + scratch zeroing
    k_sort<<<1, 1024>>>(E);
    k_pairs2<<<(E + 7) / 8, 256>>>(E);           // sweep + fused pass-1 hist
    k_sel1<<<1, 1024>>>();
    k_hist2<<<256, 256>>>();
    k_sel2<<<3, 1024>>>();
    k_loss<<<256, 256>>>(out);
}